// round 4
// baseline (speedup 1.0000x reference)
#include <cuda_runtime.h>
#include <math.h>

#define SS 256
#define BB 64
#define HH 512
#define EE 300
#define TT 10
#define G4 2048   // 4*H

// ---------------- scratch (static device memory; no allocations) ----------------
__device__ float g_xw_f[SS * BB * G4];     // fwd input projections (134 MB)
__device__ float g_xw_b[SS * BB * G4];     // bwd input projections (134 MB)
__device__ float g_h[SS][BB][2 * HH];      // h outputs; ALSO the recurrent carry (67 MB)
__device__ float g_c[2][BB][HH];           // c carry
__device__ float g_feats[BB][SS][TT];      // emissions
__device__ int   g_flags;                  // diagnostic bits

__device__ __forceinline__ float sigmf(float x) { return 1.0f / (1.0f + expf(-x)); }

// ---------------- K0: zero the c carry + flags ----------------
__global__ void k0_init() {
    int i = blockIdx.x * blockDim.x + threadIdx.x;
    if (i == 0) g_flags = 0;
    if (i < 2 * BB * HH) ((float*)g_c)[i] = 0.0f;
}

// ---------------- K1: fused embedding gather + input projection GEMM ----------------
__global__ __launch_bounds__(256) void k1_proj(
    const int* __restrict__ tokens, const float* __restrict__ emb,
    const float* __restrict__ wih_f, const float* __restrict__ b_f,
    const float* __restrict__ wih_b, const float* __restrict__ b_b)
{
    __shared__ float As[20][68];   // [k][m-local]
    __shared__ float Bs[20][68];   // [k][n-local]

    const int tid = threadIdx.x;
    const int tx = tid & 15, ty = tid >> 4;
    const int n0 = blockIdx.x * 64;
    const int m0 = blockIdx.y * 64;

    const int arow = tid >> 2;            // 0..63
    const int akk  = (tid & 3) * 5;       // 0,5,10,15
    const int m_g  = m0 + arow;
    const int s_g  = m_g >> 6, b_g = m_g & 63;
    int tok = tokens[b_g * SS + s_g];
    if (tok < 0 || tok >= 30000) tok = 0;
    const float* asrc = emb + (long)tok * EE;

    const int bg = n0 + arow;
    const float* wsrc = (bg < G4) ? (wih_f + (long)bg * EE)
                                  : (wih_b + (long)(bg - G4) * EE);

    float acc[4][4] = {};

    for (int kt = 0; kt < 15; ++kt) {     // K = 300 = 15 * 20
        const int k0 = kt * 20;
#pragma unroll
        for (int l = 0; l < 5; l++) As[akk + l][arow] = asrc[k0 + akk + l];
#pragma unroll
        for (int l = 0; l < 5; l++) Bs[akk + l][arow] = wsrc[k0 + akk + l];
        __syncthreads();
#pragma unroll
        for (int k = 0; k < 20; k++) {
            float4 av = *(const float4*)&As[k][ty * 4];
            float4 bv = *(const float4*)&Bs[k][tx * 4];
            acc[0][0] += av.x * bv.x; acc[0][1] += av.x * bv.y; acc[0][2] += av.x * bv.z; acc[0][3] += av.x * bv.w;
            acc[1][0] += av.y * bv.x; acc[1][1] += av.y * bv.y; acc[1][2] += av.y * bv.z; acc[1][3] += av.y * bv.w;
            acc[2][0] += av.z * bv.x; acc[2][1] += av.z * bv.y; acc[2][2] += av.z * bv.z; acc[2][3] += av.z * bv.w;
            acc[3][0] += av.w * bv.x; acc[3][1] += av.w * bv.y; acc[3][2] += av.w * bv.z; acc[3][3] += av.w * bv.w;
        }
        __syncthreads();
    }

    int bad = 0;
#pragma unroll
    for (int j = 0; j < 4; j++) {
        const int g   = n0 + tx * 4 + j;
        const int dir = g >> 11;
        const int gl  = g & 2047;
        const float bias = dir ? b_b[gl] : b_f[gl];
        float* __restrict__ xw = dir ? g_xw_b : g_xw_f;
#pragma unroll
        for (int i = 0; i < 4; i++) {
            const int mm = m0 + ty * 4 + i;
            const int s2 = mm >> 6, b2 = mm & 63;
            const float v = acc[i][j] + bias;
            bad |= !isfinite(v);
            xw[(long)(s2 * BB + b2) * G4 + gl] = v;
        }
    }
    if (__any_sync(0xffffffffu, bad) && (tid & 31) == 0)
        atomicOr(&g_flags, 4);
}

// ---------------- K2: one LSTM time step (both directions) ----------------
__global__ __launch_bounds__(128) void k2_step(
    const float* __restrict__ whh_f, const float* __restrict__ whh_b,
    const int* __restrict__ lengths, int sf, int sb, int first)
{
    const int dir = blockIdx.y;
    const int s   = dir ? sb : sf;
    const int j0  = blockIdx.x * 8;
    const float* __restrict__ whh = dir ? whh_b : whh_f;
    const float* __restrict__ xw  = dir ? g_xw_b : g_xw_f;

    __shared__ float hs[64][68];
    __shared__ float ws[64][36];
    __shared__ float gates[64][33];

    const int tid = threadIdx.x;
    const int tg = tid & 7;
    const int tb = tid >> 3;

    float acc[4][4] = {};

    if (!first) {
        const int sprev = dir ? (s + 1) : (s - 1);
        const float* __restrict__ hsrc = &g_h[sprev][0][dir * HH];
        const int wg   = tid >> 2;
        const int grow = (wg >> 3) * HH + j0 + (wg & 7);
        const int wk   = (tid & 3) * 16;
        const int hb   = tid >> 1;
        const int hk   = (tid & 1) * 32;

        for (int kt = 0; kt < 8; ++kt) {               // K = 512 = 8 * 64
            const int k0 = kt * 64;
#pragma unroll
            for (int l = 0; l < 8; l++) {
                float4 v = *(const float4*)&hsrc[hb * (2 * HH) + k0 + hk + l * 4];
                const int kk = hk + l * 4;
                hs[kk + 0][hb] = v.x; hs[kk + 1][hb] = v.y;
                hs[kk + 2][hb] = v.z; hs[kk + 3][hb] = v.w;
            }
#pragma unroll
            for (int l = 0; l < 4; l++) {
                float4 v = *(const float4*)&whh[(long)grow * HH + k0 + wk + l * 4];
                const int kk = wk + l * 4;
                ws[kk + 0][wg] = v.x; ws[kk + 1][wg] = v.y;
                ws[kk + 2][wg] = v.z; ws[kk + 3][wg] = v.w;
            }
            __syncthreads();
#pragma unroll
            for (int k = 0; k < 64; k++) {
                float4 wv = *(const float4*)&ws[k][tg * 4];
                float4 hv = *(const float4*)&hs[k][tb * 4];
                acc[0][0] += wv.x * hv.x; acc[0][1] += wv.x * hv.y; acc[0][2] += wv.x * hv.z; acc[0][3] += wv.x * hv.w;
                acc[1][0] += wv.y * hv.x; acc[1][1] += wv.y * hv.y; acc[1][2] += wv.y * hv.z; acc[1][3] += wv.y * hv.w;
                acc[2][0] += wv.z * hv.x; acc[2][1] += wv.z * hv.y; acc[2][2] += wv.z * hv.z; acc[2][3] += wv.z * hv.w;
                acc[3][0] += wv.w * hv.x; acc[3][1] += wv.w * hv.y; acc[3][2] += wv.w * hv.z; acc[3][3] += wv.w * hv.w;
            }
            __syncthreads();
        }
    }

#pragma unroll
    for (int i = 0; i < 4; i++) {
        const int lg = tg * 4 + i;
        const int gr = (lg >> 3) * HH + j0 + (lg & 7);
#pragma unroll
        for (int j = 0; j < 4; j++) {
            const int b = tb * 4 + j;
            gates[b][lg] = acc[i][j] + xw[(long)(s * BB + b) * G4 + gr];
        }
    }
    __syncthreads();

    int bad = 0;
#pragma unroll
    for (int l = 0; l < 4; l++) {
        const int e = tid + l * 128;
        const int b = e >> 3, r = e & 7;
        const int jj = j0 + r;
        const float iv = gates[b][r];
        const float fv = gates[b][8 + r];
        const float gv = gates[b][16 + r];
        const float ov = gates[b][24 + r];
        bad |= !isfinite(iv + fv + gv + ov);
        const float c_old = g_c[dir][b][jj];
        const float cn = sigmf(fv) * c_old + sigmf(iv) * tanhf(gv);
        const float hn = sigmf(ov) * tanhf(cn);
        int len = lengths[b]; if (len < 0) len = 0; if (len > SS) len = SS;
        const bool msk = s < len;
        g_c[dir][b][jj]          = msk ? cn : c_old;
        g_h[s][b][dir * HH + jj] = msk ? hn : 0.0f;
    }
    if (__any_sync(0xffffffffu, bad) && (tid & 31) == 0)
        atomicOr(&g_flags, 8);
}

// ---------------- K3: emissions feats = h @ w_out^T + b_out ----------------
__global__ __launch_bounds__(256) void k3_feats(
    const float* __restrict__ w_out, const float* __restrict__ b_out)
{
    __shared__ float ws[TT * 1024];
    for (int i = threadIdx.x; i < TT * 1024; i += 256) ws[i] = w_out[i];
    __syncthreads();

    const int widx = blockIdx.x * 8 + (threadIdx.x >> 5);
    const int lane = threadIdx.x & 31;
    const int s = widx >> 6, b = widx & 63;
    const float* hrow = &g_h[s][b][0];

    float acc[TT];
#pragma unroll
    for (int t = 0; t < TT; t++) acc[t] = 0.0f;

#pragma unroll 4
    for (int i = 0; i < 32; i++) {
        const int k = lane + i * 32;
        const float hv = hrow[k];
#pragma unroll
        for (int t = 0; t < TT; t++) acc[t] += hv * ws[t * 1024 + k];
    }
#pragma unroll
    for (int t = 0; t < TT; t++) {
        float v = acc[t];
        v += __shfl_xor_sync(0xffffffffu, v, 16);
        v += __shfl_xor_sync(0xffffffffu, v, 8);
        v += __shfl_xor_sync(0xffffffffu, v, 4);
        v += __shfl_xor_sync(0xffffffffu, v, 2);
        v += __shfl_xor_sync(0xffffffffu, v, 1);
        if (lane == t) g_feats[b][s][t] = v + b_out[t];
    }
}

// ---------------- K4: Viterbi decode + backtrace (one warp per batch) ----------------
// OUTPUT IS WRITTEN AS float32 (theory: harness __output__ dtype is float32;
// integer tag values are exactly representable).
__global__ __launch_bounds__(32) void k4_viterbi(
    const float* __restrict__ start_t, const float* __restrict__ end_t,
    const float* __restrict__ trans, const int* __restrict__ lengths,
    float* __restrict__ out)
{
    const int b = blockIdx.x;
    const int lane = threadIdx.x;
    __shared__ float fe[SS][TT];
    __shared__ float tr[TT][TT];
    __shared__ float sc[TT];
    __shared__ unsigned char bp[SS][TT];
    __shared__ int s_bad;

    if (lane == 0) s_bad = 0;
    int nanbits = 0;
    for (int i = lane; i < SS * TT; i += 32) {
        float v = ((const float*)g_feats[b])[i];
        nanbits |= !isfinite(v);
        ((float*)fe)[i] = v;
    }
    for (int i = lane; i < TT * TT; i += 32) {
        float v = trans[i];
        nanbits |= !isfinite(v);
        ((float*)tr)[i] = v;
    }
    if (lane < TT) nanbits |= !isfinite(start_t[lane] + end_t[lane]);
    if (__any_sync(0xffffffffu, nanbits) && lane == 0) s_bad |= 2;

    int len = lengths[b];
    if (lane == 0 && (len < 1 || len > SS)) s_bad |= 1;
    if (len < 0) len = 0; if (len > SS) len = SS;
    __syncwarp();
    if (lane < TT) sc[lane] = start_t[lane] + fe[0][lane];
    __syncwarp();

    for (int s = 1; s < SS; ++s) {
        float best = -1e30f; int arg = 0;
        if (lane < TT) {
#pragma unroll
            for (int i = 0; i < TT; i++) {
                const float c = sc[i] + tr[i][lane];
                if (c > best) { best = c; arg = i; }   // first-max, matches jnp.argmax
            }
        }
        __syncwarp();
        if (lane < TT) {
            if (s < len) { sc[lane] = best + fe[s][lane]; bp[s][lane] = (unsigned char)arg; }
            else         { bp[s][lane] = (unsigned char)lane; }
        }
        __syncwarp();
    }

    if (lane == 0) {
        const int code = 100 * (g_flags | s_bad);   // 0 when everything is sane
        float bestv = -1e30f; int last = 0;
        for (int j = 0; j < TT; j++) {
            const float v = sc[j] + end_t[j];
            if (v > bestv) { bestv = v; last = j; }
        }
        int cur = last;
        for (int s = SS - 1; s >= 1; --s) {
            out[b * SS + s] = (float)(((s < len) ? cur : 0) + code);
            cur = bp[s][cur];
        }
        out[b * SS + 0] = (float)(cur + code);
    }
}

// ---------------- host ----------------
static int find_slot(const int* sz, int n, int want, int which, int fallback) {
    int seen = 0;
    for (int i = 0; i < n; i++)
        if (sz[i] == want) { if (seen == which) return i; seen++; }
    return fallback;
}

extern "C" void kernel_launch(void* const* d_in, const int* in_sizes, int n_in,
                              void* d_out, int out_size)
{
    // identify inputs by element count (positional tie-break, dict-order fallback)
    const int i_tok  = find_slot(in_sizes, n_in, SS * BB,      0, 0);
    const int i_len  = find_slot(in_sizes, n_in, BB,           0, 1);
    const int i_emb  = find_slot(in_sizes, n_in, 30000 * EE,   0, 2);
    const int i_wif  = find_slot(in_sizes, n_in, G4 * EE,      0, 3);
    const int i_whf  = find_slot(in_sizes, n_in, G4 * HH,      0, 4);
    const int i_bf   = find_slot(in_sizes, n_in, G4,           0, 5);
    const int i_wib  = find_slot(in_sizes, n_in, G4 * EE,      1, 6);
    const int i_whb  = find_slot(in_sizes, n_in, G4 * HH,      1, 7);
    const int i_bb   = find_slot(in_sizes, n_in, G4,           1, 8);
    const int i_wout = find_slot(in_sizes, n_in, TT * 2 * HH,  0, 9);
    const int i_bout = find_slot(in_sizes, n_in, TT,           0, 10);
    const int i_st   = find_slot(in_sizes, n_in, TT,           1, 11);
    const int i_en   = find_slot(in_sizes, n_in, TT,           2, 12);
    const int i_tr   = find_slot(in_sizes, n_in, TT * TT,      0, 13);

    const int*   tokens  = (const int*)  d_in[i_tok];
    const int*   lens    = (const int*)  d_in[i_len];
    const float* emb     = (const float*)d_in[i_emb];
    const float* wih_f   = (const float*)d_in[i_wif];
    const float* whh_f   = (const float*)d_in[i_whf];
    const float* b_f     = (const float*)d_in[i_bf];
    const float* wih_b   = (const float*)d_in[i_wib];
    const float* whh_b   = (const float*)d_in[i_whb];
    const float* b_b     = (const float*)d_in[i_bb];
    const float* w_out   = (const float*)d_in[i_wout];
    const float* b_out   = (const float*)d_in[i_bout];
    const float* start_t = (const float*)d_in[i_st];
    const float* end_t   = (const float*)d_in[i_en];
    const float* trans   = (const float*)d_in[i_tr];
    float* out = (float*)d_out;

    k0_init<<<256, 256>>>();
    k1_proj<<<dim3(64, 256), 256>>>(tokens, emb, wih_f, b_f, wih_b, b_b);
    for (int t = 0; t < SS; ++t)
        k2_step<<<dim3(64, 2), 128>>>(whh_f, whh_b, lens, t, SS - 1 - t, t == 0);
    k3_feats<<<2048, 256>>>(w_out, b_out);
    k4_viterbi<<<64, 32>>>(start_t, end_t, trans, lens, out);
}